// round 1
// baseline (speedup 1.0000x reference)
#include <cuda_runtime.h>
#include <cuda_bf16.h>

// Problem constants
#define BB    32
#define CC    64
#define HH    64
#define WW    64
#define HW    (HH * WW)          // 4096
#define NE    512                // codebook entries
#define NTOK  (BB * HW)          // 131072 tokens
#define BCHW  (BB * CC * HW)     // 8388608
#define BHW   (BB * HW)          // 131072

// Tile config for the fused distance+argmax kernel
#define TT    256                // tokens per CTA
#define NTH   512                // threads per CTA
#define KCH   64                 // K (feature dim)

// smem layout sizes (floats)
#define ES_FLOATS (KCH * NE)     // 32768  (codebook, K-major: Es[k][j])
#define XS_FLOATS (KCH * TT)     // 16384  (token tile, K-major: Xs[k][t])
#define HN_FLOATS (NE)           // 512
#define SMEM_BYTES ((ES_FLOATS + XS_FLOATS + HN_FLOATS) * 4)  // 198656

// Scratch for argmin indices (device global: no allocations allowed)
__device__ int g_ind[NTOK];

// ---------------------------------------------------------------------------
// Kernel 1: fused distance GEMM + argmax.
// Each CTA: 256 tokens of one batch vs all 512 codes.
// Threads: 512 = 32 (ty, token groups of 8) x 16 (tx, code groups of 8).
// ---------------------------------------------------------------------------
__global__ void __launch_bounds__(NTH, 1)
vq_argmin_kernel(const float* __restrict__ x,
                 const float* __restrict__ embed,   // [C=64][NE=512]
                 int* __restrict__ ind)
{
    extern __shared__ float smem[];
    float* Es = smem;                    // [64][512]
    float* Xs = Es + ES_FLOATS;          // [64][256]
    float* Hn = Xs + XS_FLOATS;          // [512]

    const int tid = threadIdx.x;
    const int tx  = tid & 15;            // code lane 0..15
    const int ty  = tid >> 4;            // token lane 0..31

    const int blk   = blockIdx.x;        // 0..511
    const int b     = blk >> 4;          // batch
    const int t0    = (blk & 15) * TT;   // token offset within batch

    // --- load codebook (same layout as global: [c][j]) ---
    {
        const float4* src = (const float4*)embed;
        float4* dst = (float4*)Es;
        #pragma unroll
        for (int it = 0; it < (ES_FLOATS / 4) / NTH; it++)
            dst[tid + it * NTH] = src[tid + it * NTH];
    }

    // --- load token tile transposed: Xs[c][t] from NCHW input ---
    {
        const float4* xin = (const float4*)(x + (size_t)b * (CC * HW) + t0);
        float4* dst = (float4*)Xs;
        #pragma unroll
        for (int it = 0; it < (XS_FLOATS / 4) / NTH; it++) {
            int i = tid + it * NTH;      // i = c*64 + v  (v: float4 within row)
            int c = i >> 6;
            int v = i & 63;
            dst[i] = xin[c * (HW / 4) + v];
        }
    }
    __syncthreads();

    // --- half-norms: Hn[j] = 0.5 * sum_c Es[c][j]^2 ---
    if (tid < NE) {
        float s = 0.f;
        #pragma unroll
        for (int c = 0; c < KCH; c++) {
            float e = Es[c * NE + tid];
            s = fmaf(e, e, s);
        }
        Hn[tid] = 0.5f * s;
    }
    __syncthreads();

    // --- main: 8 tokens x 8 codes per thread, 4 code-chunks of 128 ---
    const int trow = ty * 8;             // token base for this thread
    float best[8];
    int   bidx[8];
    #pragma unroll
    for (int i = 0; i < 8; i++) { best[i] = -3.4e38f; bidx[i] = 0; }

    #pragma unroll
    for (int chunk = 0; chunk < 4; chunk++) {
        const int cbase = chunk * 128 + tx * 8;
        float acc[8][8];
        #pragma unroll
        for (int i = 0; i < 8; i++)
            #pragma unroll
            for (int j = 0; j < 8; j++) acc[i][j] = 0.f;

        #pragma unroll 8
        for (int k = 0; k < KCH; k++) {
            float4 a0 = *(const float4*)(Xs + k * TT + trow);
            float4 a1 = *(const float4*)(Xs + k * TT + trow + 4);
            float4 b0 = *(const float4*)(Es + k * NE + cbase);
            float4 b1 = *(const float4*)(Es + k * NE + cbase + 4);
            float av[8] = {a0.x, a0.y, a0.z, a0.w, a1.x, a1.y, a1.z, a1.w};
            float bv[8] = {b0.x, b0.y, b0.z, b0.w, b1.x, b1.y, b1.z, b1.w};
            #pragma unroll
            for (int i = 0; i < 8; i++)
                #pragma unroll
                for (int j = 0; j < 8; j++)
                    acc[i][j] = fmaf(av[i], bv[j], acc[i][j]);
        }

        // fold chunk into running argmax (score = dot - halfnorm)
        #pragma unroll
        for (int j = 0; j < 8; j++) {
            float h = Hn[cbase + j];
            int   cj = cbase + j;
            #pragma unroll
            for (int i = 0; i < 8; i++) {
                float s = acc[i][j] - h;
                if (s > best[i] || (s == best[i] && cj < bidx[i])) {
                    best[i] = s; bidx[i] = cj;
                }
            }
        }
    }

    // --- reduce across the 16 code-lanes (half-warp shuffle) ---
    #pragma unroll
    for (int i = 0; i < 8; i++) {
        float s = best[i];
        int   j = bidx[i];
        #pragma unroll
        for (int o = 8; o >= 1; o >>= 1) {
            float so = __shfl_xor_sync(0xffffffffu, s, o);
            int   jo = __shfl_xor_sync(0xffffffffu, j, o);
            if (so > s || (so == s && jo < j)) { s = so; j = jo; }
        }
        if (tx == 0)
            ind[b * HW + t0 + trow + i] = j;
    }
}

// ---------------------------------------------------------------------------
// Kernel 2: gather codebook -> NCHW outputs (+ indices as float).
// out layout: [quantize_with_grad (BCHW)] [quantize (BCHW)] [ind (BHW)]
// ---------------------------------------------------------------------------
__global__ void vq_gather_kernel(const float* __restrict__ embed,
                                 const int* __restrict__ ind,
                                 float* __restrict__ o_qwg,
                                 float* __restrict__ o_q,
                                 float* __restrict__ o_ind)
{
    int n = blockIdx.x * blockDim.x + threadIdx.x;   // 0 .. BCHW-1
    if (n < BCHW) {
        int t  = n & (HW - 1);           // hw position
        int c  = (n >> 12) & (CC - 1);   // channel
        int b  = n >> 18;                // batch
        int id = ind[b * HW + t];
        float v = embed[c * NE + id];
        o_qwg[n] = v;
        if (o_q) o_q[n] = v;
    }
    if (o_ind && n < BHW)
        o_ind[n] = (float)ind[n];
}

// ---------------------------------------------------------------------------
extern "C" void kernel_launch(void* const* d_in, const int* in_sizes, int n_in,
                              void* d_out, int out_size)
{
    const float* x     = (const float*)d_in[0];   // [B,C,H,W] fp32
    const float* embed = (const float*)d_in[1];   // [C, NE]   fp32
    float* out = (float*)d_out;

    int* ind;
    cudaGetSymbolAddress((void**)&ind, g_ind);

    cudaFuncSetAttribute(vq_argmin_kernel,
                         cudaFuncAttributeMaxDynamicSharedMemorySize, SMEM_BYTES);

    // Kernel 1: indices
    vq_argmin_kernel<<<NTOK / TT, NTH, SMEM_BYTES>>>(x, embed, ind);

    // Output region mapping (defensive on out_size)
    float* o_qwg = out;
    float* o_q   = nullptr;
    float* o_ind = nullptr;
    long os = out_size;
    if (os >= 2L * BCHW + BHW)      { o_q = out + BCHW; o_ind = out + 2L * BCHW; }
    else if (os >= 2L * BCHW)       { o_q = out + BCHW; }
    else if (os >= (long)BCHW + BHW){ o_ind = out + BCHW; }

    // Kernel 2: gather + writes
    vq_gather_kernel<<<(BCHW + 255) / 256, 256>>>(embed, ind, o_qwg, o_q, o_ind);
}

// round 3
// speedup vs baseline: 1.7519x; 1.7519x over previous
#include <cuda_runtime.h>
#include <cuda_fp16.h>
#include <cstdint>

// ---------------- problem constants ----------------
#define BB    32
#define CC    64
#define HW    4096
#define NE    512
#define BCHW  (BB * CC * HW)     // 8388608
#define BHW   (BB * HW)          // 131072
#define MTILE 64                 // tokens per CTA iteration
#define NBLK  (BHW / MTILE)      // 2048
#define NTH   256
#define GRID  148

// ---------------- smem layout (bytes) ----------------
// A:   [k=128 rows][m pad 72 halves]  -> row stride 144 B, 18432 B
// B:   [n=512 rows][k pad 136 halves] -> row stride 272 B, 139264 B
//      (cols 0-63 = e1, cols 64-127 = e2)
// HN:  512 f32
// PART:[64 tokens][9] u64 (pad col to kill bank conflicts)
// INDS: 64 int
#define A_OFF   0
#define A_ROW   144
#define B_OFF   18432
#define B_ROW   272
#define HN_OFF  (B_OFF + NE * B_ROW)          // 157696
#define PART_OFF (HN_OFF + 2048)              // 159744
#define IND_OFF (PART_OFF + 64 * 9 * 8)       // 164352
#define SMEM_BYTES (IND_OFF + 256)            // 164608

// ---------------- helpers ----------------
__device__ __forceinline__ uint32_t smem_u32(const void* p) {
    uint32_t a;
    asm("{ .reg .u64 t; cvta.to.shared.u64 t, %1; cvt.u32.u64 %0, t; }" : "=r"(a) : "l"(p));
    return a;
}
__device__ __forceinline__ void ldsm_x4(uint32_t* r, uint32_t addr) {
    asm volatile("ldmatrix.sync.aligned.m8n8.x4.shared.b16 {%0,%1,%2,%3}, [%4];"
                 : "=r"(r[0]), "=r"(r[1]), "=r"(r[2]), "=r"(r[3]) : "r"(addr));
}
__device__ __forceinline__ void ldsm_x4_t(uint32_t* r, uint32_t addr) {
    asm volatile("ldmatrix.sync.aligned.m8n8.x4.trans.shared.b16 {%0,%1,%2,%3}, [%4];"
                 : "=r"(r[0]), "=r"(r[1]), "=r"(r[2]), "=r"(r[3]) : "r"(addr));
}
__device__ __forceinline__ void mma16816(float* d, const uint32_t* a, const uint32_t* b) {
    asm volatile("mma.sync.aligned.m16n8k16.row.col.f32.f16.f16.f32 "
                 "{%0,%1,%2,%3}, {%4,%5,%6,%7}, {%8,%9}, {%0,%1,%2,%3};"
                 : "+f"(d[0]), "+f"(d[1]), "+f"(d[2]), "+f"(d[3])
                 : "r"(a[0]), "r"(a[1]), "r"(a[2]), "r"(a[3]), "r"(b[0]), "r"(b[1]));
}
__device__ __forceinline__ uint32_t fmono(float f) {
    uint32_t u = __float_as_uint(f);
    return (u & 0x80000000u) ? ~u : (u | 0x80000000u);
}
__device__ __forceinline__ unsigned long long umax64(unsigned long long a, unsigned long long b) {
    return a > b ? a : b;
}

// ---------------------------------------------------------------------------
// Persistent fused kernel: fp16x3 mma.sync GEMM + argmax + gather + writes.
// ---------------------------------------------------------------------------
__global__ void __launch_bounds__(NTH, 1)
vq_kernel(const float* __restrict__ x, const float* __restrict__ embed,
          float* __restrict__ o_qwg, float* __restrict__ o_q, float* __restrict__ o_ind)
{
    extern __shared__ char smem[];
    const uint32_t sb = smem_u32(smem);
    const int tid  = threadIdx.x;
    const int lane = tid & 31;
    const int w    = tid >> 5;           // warp 0..7, owns codes [w*64, w*64+64)

    // ---- codebook conversion + halfnorms (once per CTA) ----
    #pragma unroll
    for (int jj = 0; jj < 2; jj++) {
        int j = tid + jj * 256;          // code 0..511
        float s = 0.f;
        #pragma unroll 8
        for (int k = 0; k < 64; k++) {
            float val = __ldg(&embed[k * NE + j]);   // coalesced across lanes
            half h1 = __float2half_rn(val);
            half h2 = __float2half_rn(val - __half2float(h1));
            *(half*)(smem + B_OFF + j * B_ROW + k * 2)       = h1;
            *(half*)(smem + B_OFF + j * B_ROW + 128 + k * 2) = h2;
            s = fmaf(val, val, s);
        }
        ((float*)(smem + HN_OFF))[j] = 0.5f * s;
    }
    __syncthreads();

    // lane-invariant ldmatrix address parts
    const int lrow = ((lane & 16) >> 1) + (lane & 7);
    const uint32_t a_lane = sb + A_OFF + (uint32_t)lrow * A_ROW + (lane & 8) * 2;
    const uint32_t b_lane = sb + B_OFF + (uint32_t)(w * 64 + lrow) * B_ROW + (lane & 8) * 2;

    // k-step schedule: x1*e1, x1*e2, x2*e1  (A rows: x1=0-63, x2=64-127; B cols: e1=0-63, e2=64-127)
    const int KA[12] = {0,16,32,48,  0,16,32,48, 64,80,96,112};
    const int KB[12] = {0,16,32,48, 64,80,96,112, 0,16,32,48};

    const float* HN = (const float*)(smem + HN_OFF);
    unsigned long long* PART = (unsigned long long*)(smem + PART_OFF);
    int* INDS = (int*)(smem + IND_OFF);
    const int g = lane >> 2, tig = lane & 3;
    const int n0 = w * 64;

    for (int tb = blockIdx.x; tb < NBLK; tb += GRID) {
        const int b  = tb >> 6;
        const int t0 = (tb & 63) << 6;

        // -- load x tile: 64 tokens x 64 channels (coalesced float4) --
        float4 f[4];
        const float4* xin = (const float4*)(x + (size_t)b * CC * HW) + (t0 >> 2);
        #pragma unroll
        for (int i = 0; i < 4; i++) {
            int idx = tid + i * 256;
            f[i] = xin[(idx >> 4) * (HW / 4) + (idx & 15)];
        }

        // -- split to fp16 and store A[k][m] --
        #pragma unroll
        for (int i = 0; i < 4; i++) {
            int idx = tid + i * 256;
            int c = idx >> 4, v = idx & 15;
            float vals[4] = {f[i].x, f[i].y, f[i].z, f[i].w};
            #pragma unroll
            for (int p = 0; p < 2; p++) {
                float va = vals[2 * p], vb = vals[2 * p + 1];
                half a1 = __float2half_rn(va);
                half b1 = __float2half_rn(vb);
                half a2 = __float2half_rn(va - __half2float(a1));
                half b2 = __float2half_rn(vb - __half2float(b1));
                int m = 4 * v + 2 * p;
                *(half2*)(smem + A_OFF + c * A_ROW + m * 2)        = __halves2half2(a1, b1);
                *(half2*)(smem + A_OFF + (64 + c) * A_ROW + m * 2) = __halves2half2(a2, b2);
            }
        }
        __syncthreads();

        // -- GEMM: warp tile m64 x n64, K=192 via 12 k-steps --
        float acc[4][8][4];
        #pragma unroll
        for (int mt = 0; mt < 4; mt++)
            #pragma unroll
            for (int ni = 0; ni < 8; ni++)
                #pragma unroll
                for (int r = 0; r < 4; r++) acc[mt][ni][r] = 0.f;

        #pragma unroll
        for (int s = 0; s < 12; s++) {
            uint32_t af[4][4], bf[4][4];
            #pragma unroll
            for (int mt = 0; mt < 4; mt++)
                ldsm_x4_t(af[mt], a_lane + KA[s] * A_ROW + mt * 32);
            #pragma unroll
            for (int nt = 0; nt < 4; nt++)
                ldsm_x4(bf[nt], b_lane + nt * 16 * B_ROW + KB[s] * 2);
            #pragma unroll
            for (int mt = 0; mt < 4; mt++)
                #pragma unroll
                for (int nt = 0; nt < 4; nt++) {
                    mma16816(acc[mt][nt * 2],     af[mt], &bf[nt][0]);
                    mma16816(acc[mt][nt * 2 + 1], af[mt], &bf[nt][2]);
                }
        }

        // -- fused argmax epilogue --
        float hn[8][2];
        #pragma unroll
        for (int ni = 0; ni < 8; ni++) {
            hn[ni][0] = HN[n0 + ni * 8 + 2 * tig];
            hn[ni][1] = HN[n0 + ni * 8 + 2 * tig + 1];
        }
        #pragma unroll
        for (int mt = 0; mt < 4; mt++) {
            #pragma unroll
            for (int rh = 0; rh < 2; rh++) {
                unsigned long long best = 0ull;
                #pragma unroll
                for (int ni = 0; ni < 8; ni++) {
                    #pragma unroll
                    for (int hc = 0; hc < 2; hc++) {
                        float sc = acc[mt][ni][rh * 2 + hc] - hn[ni][hc];
                        int col = n0 + ni * 8 + 2 * tig + hc;
                        unsigned long long p =
                            ((unsigned long long)fmono(sc) << 32) | (unsigned)(511 - col);
                        best = umax64(best, p);
                    }
                }
                best = umax64(best, __shfl_xor_sync(0xffffffffu, best, 1));
                best = umax64(best, __shfl_xor_sync(0xffffffffu, best, 2));
                if (tig == 0)
                    PART[(mt * 16 + rh * 8 + g) * 9 + w] = best;
            }
        }
        __syncthreads();

        if (tid < 64) {
            unsigned long long m = PART[tid * 9];
            #pragma unroll
            for (int ww = 1; ww < 8; ww++) m = umax64(m, PART[tid * 9 + ww]);
            int code = 511 - (int)(unsigned)(m & 0xffffffffu);
            INDS[tid] = code;
            if (o_ind) o_ind[(size_t)b * HW + t0 + tid] = (float)code;
        }
        __syncthreads();

        // -- fused gather + NCHW writes (both outputs) --
        #pragma unroll
        for (int i = 0; i < 4; i++) {
            int idx = tid + i * 256;
            int c = idx >> 4, v = idx & 15;
            float4 o;
            float* op = &o.x;
            #pragma unroll
            for (int e = 0; e < 4; e++) {
                int code = INDS[4 * v + e];
                float v1 = __half2float(*(const half*)(smem + B_OFF + code * B_ROW + c * 2));
                float v2 = __half2float(*(const half*)(smem + B_OFF + code * B_ROW + 128 + c * 2));
                op[e] = v1 + v2;
            }
            size_t off = (size_t)b * CC * HW + (size_t)c * HW + t0 + 4 * v;
            *(float4*)(o_qwg + off) = o;
            if (o_q) *(float4*)(o_q + off) = o;
        }
        // next iteration's first __syncthreads (after A store) orders gather vs reuse
    }
}

// ---------------------------------------------------------------------------
extern "C" void kernel_launch(void* const* d_in, const int* in_sizes, int n_in,
                              void* d_out, int out_size)
{
    const float* x     = (const float*)d_in[0];
    const float* embed = (const float*)d_in[1];
    float* out = (float*)d_out;

    float* o_qwg = out;
    float* o_q   = nullptr;
    float* o_ind = nullptr;
    long os = out_size;
    if (os >= 2L * BCHW + BHW)       { o_q = out + BCHW; o_ind = out + 2L * BCHW; }
    else if (os >= 2L * BCHW)        { o_q = out + BCHW; }
    else if (os >= (long)BCHW + BHW) { o_ind = out + BCHW; }

    cudaFuncSetAttribute(vq_kernel,
                         cudaFuncAttributeMaxDynamicSharedMemorySize, SMEM_BYTES);

    vq_kernel<<<GRID, NTH, SMEM_BYTES>>>(x, embed, o_qwg, o_q, o_ind);
}